// round 4
// baseline (speedup 1.0000x reference)
#include <cuda_runtime.h>
#include <cuda_bf16.h>
#include <cstdint>

#define HW_ 256
#define C_  32
#define O_  32
#define B_  8

// gate scratch (allowed: __device__ global array)
__device__ float g_gate[B_ * HW_ * HW_];

__device__ __forceinline__ float sigf(float v) {
    float t; asm("tanh.approx.f32 %0, %1;" : "=f"(t) : "f"(v * 0.5f));
    return fmaf(0.5f, t, 0.5f);
}

// ================== kernel 1: gate ==================
#define G_TW  32
#define G_TH  16
#define G_STR 36
#define G_CSZ (18 * G_STR)
#define G_SMEM ((C_ * G_CSZ + 288) * 4)

__global__ __launch_bounds__(256)
void gate_kernel(const float* __restrict__ x, const float* __restrict__ dweight)
{
    extern __shared__ float sm1[];
    float* sg  = sm1;
    float* dws = sm1 + C_ * G_CSZ;

    const int tid = threadIdx.x;
    const int b   = blockIdx.z;
    const int x0  = blockIdx.x * G_TW;
    const int y0  = blockIdx.y * G_TH;
    const float* xb = x + (size_t)b * C_ * HW_ * HW_;

    for (int i = tid; i < 288; i += 256) dws[i] = dweight[i];

    #pragma unroll 4
    for (int i = tid; i < C_ * G_CSZ; i += 256) {
        int c   = i / G_CSZ;
        int rem = i - c * G_CSZ;
        int iy  = rem / G_STR;
        int ix  = rem - iy * G_STR;
        float v = 0.0f;
        if (ix < 34) {
            int gy = y0 + iy - 1, gx = x0 + ix - 1;
            if ((unsigned)gy < HW_ && (unsigned)gx < HW_)
                v = xb[c * HW_ * HW_ + gy * HW_ + gx];
        }
        sg[i] = sigf(v);
    }
    __syncthreads();

    const int pr  = tid & 15;
    const int row = tid >> 4;
    const int px0 = pr * 2;

    float g0 = 0.0f, g1 = 0.0f;
    for (int c = 0; c < C_; c++) {
        const float* dc = dws + c * 9;
        const float* s  = sg + c * G_CSZ + row * G_STR + px0;
        #pragma unroll
        for (int ki = 0; ki < 3; ki++) {
            float2 a  = *(const float2*)(s + ki * G_STR);
            float2 bb = *(const float2*)(s + ki * G_STR + 2);
            float d0 = dc[ki*3], d1 = dc[ki*3+1], d2 = dc[ki*3+2];
            g0 = fmaf(d0, a.x,  g0); g0 = fmaf(d1, a.y,  g0); g0 = fmaf(d2, bb.x, g0);
            g1 = fmaf(d0, a.y,  g1); g1 = fmaf(d1, bb.x, g1); g1 = fmaf(d2, bb.y, g1);
        }
    }
    *(float2*)(&g_gate[((size_t)b * HW_ + (y0 + row)) * HW_ + x0 + px0]) = make_float2(g0, g1);
}

// ================== kernel 2: conv via mma.sync bf16 (3-term split) ==================
// CTA: 1 output row x 256 px, 8 warps x (32px x 32o).
// A smem: 3 halo rows x 258 px x 32 words (+4 pad) ; word = (x_hi bf16 | x_lo bf16 <<16)
// B smem: [tap(9)][set(2)][kchunk(4)] blocks of 32o x 8kp words, o-stride 12.
//   set0 word = (w_hi | w_hi<<16), set1 word = (w_lo | 0<<16)

#define APX  36
#define AROW (258 * APX)                 // 9288 words
#define SM_A_W   32                      // after 32 bias words
#define SM_B_W   (SM_A_W + 3 * AROW)     // 27896
#define SM_TOT_W (SM_B_W + 9*2*4*384)    // 55544 words
#define SM_TOT_BYTES (SM_TOT_W * 4)      // 222176 bytes

__device__ __forceinline__ uint32_t pack_hilo(float v) {
    __nv_bfloat16 h = __float2bfloat16(v);
    float hf = __bfloat162float(h);
    __nv_bfloat16 l = __float2bfloat16(v - hf);
    uint32_t hu = __bfloat16_as_ushort(h);
    uint32_t lu = __bfloat16_as_ushort(l);
    return hu | (lu << 16);
}

__device__ __forceinline__ void mma16816(float* c, uint32_t a0, uint32_t a1,
                                         uint32_t a2, uint32_t a3,
                                         uint32_t b0, uint32_t b1) {
    asm volatile(
        "mma.sync.aligned.m16n8k16.row.col.f32.bf16.bf16.f32 "
        "{%0,%1,%2,%3}, {%4,%5,%6,%7}, {%8,%9}, {%0,%1,%2,%3};"
        : "+f"(c[0]), "+f"(c[1]), "+f"(c[2]), "+f"(c[3])
        : "r"(a0), "r"(a1), "r"(a2), "r"(a3), "r"(b0), "r"(b1));
}

__global__ __launch_bounds__(256, 1)
void conv_kernel(const float* __restrict__ x, const float* __restrict__ weight,
                 const float* __restrict__ bias, float* __restrict__ out)
{
    extern __shared__ char sm2[];
    uint32_t* smw = (uint32_t*)sm2;
    float* bias_s = (float*)sm2;

    const int tid = threadIdx.x;
    const int y   = blockIdx.x;
    const int b   = blockIdx.y;

    if (tid < 32) bias_s[tid] = bias[tid];

    // ---- A fill: 3 halo rows x 32c x 64 float4-groups (hp = 1..256) ----
    const float* xb = x + (size_t)b * C_ * HW_ * HW_;
    for (int i = tid; i < 3 * 32 * 64; i += 256) {
        int r   = i / (32 * 64);
        int rem = i - r * (32 * 64);
        int c   = rem >> 6;
        int g4  = rem & 63;
        int gy  = y - 1 + r;
        float4 v = make_float4(0.f, 0.f, 0.f, 0.f);
        if ((unsigned)gy < HW_)
            v = *(const float4*)(xb + (size_t)c * HW_ * HW_ + gy * HW_ + g4 * 4);
        int base = SM_A_W + (r * 258 + g4 * 4 + 1) * APX + c;
        smw[base]           = pack_hilo(v.x);
        smw[base + APX]     = pack_hilo(v.y);
        smw[base + 2 * APX] = pack_hilo(v.z);
        smw[base + 3 * APX] = pack_hilo(v.w);
    }
    // halo edge columns hp=0 and hp=257 -> zero
    for (int i = tid; i < 3 * 32 * 2; i += 256) {
        int r = i / 64; int rem = i - r * 64; int c = rem >> 1; int e = rem & 1;
        smw[SM_A_W + (r * 258 + e * 257) * APX + c] = 0;
    }
    // ---- B fill ----
    for (int i = tid; i < O_ * C_ * 9; i += 256) {
        float w  = weight[i];
        int o    = i / 288;
        int rem  = i - o * 288;
        int c    = rem / 9;
        int tap  = rem - c * 9;
        __nv_bfloat16 h = __float2bfloat16(w);
        float hf = __bfloat162float(h);
        __nv_bfloat16 l = __float2bfloat16(w - hf);
        uint32_t hu = __bfloat16_as_ushort(h);
        uint32_t lu = __bfloat16_as_ushort(l);
        int kch = c >> 3, kp = c & 7;
        smw[SM_B_W + ((tap * 2 + 0) * 4 + kch) * 384 + o * 12 + kp] = hu | (hu << 16);
        smw[SM_B_W + ((tap * 2 + 1) * 4 + kch) * 384 + o * 12 + kp] = lu;
    }
    __syncthreads();

    // ---- mainloop ----
    const int lane = tid & 31, warp = tid >> 5;
    const int tig  = lane & 3, grp = lane >> 2;
    const int pxw  = warp * 32;

    float acc[2][4][4];
    #pragma unroll
    for (int mb = 0; mb < 2; mb++)
        #pragma unroll
        for (int nb = 0; nb < 4; nb++)
            #pragma unroll
            for (int r = 0; r < 4; r++) acc[mb][nb][r] = 0.0f;

    int boff[4];
    #pragma unroll
    for (int nb = 0; nb < 4; nb++) boff[nb] = (nb * 8 + grp) * 12 + tig;

    #pragma unroll 1
    for (int tap = 0; tap < 9; tap++) {
        int ki = tap / 3;
        int kj = tap - ki * 3;
        int abase = SM_A_W + (ki * 258 + pxw + kj + grp) * APX + tig;
        #pragma unroll
        for (int kch = 0; kch < 4; kch++) {
            uint32_t a[2][4];
            #pragma unroll
            for (int mb = 0; mb < 2; mb++) {
                int ab = abase + mb * (16 * APX) + kch * 8;
                a[mb][0] = smw[ab];
                a[mb][1] = smw[ab + 8 * APX];
                a[mb][2] = smw[ab + 4];
                a[mb][3] = smw[ab + 8 * APX + 4];
            }
            #pragma unroll
            for (int set = 0; set < 2; set++) {
                int bb = SM_B_W + ((tap * 2 + set) * 4 + kch) * 384;
                #pragma unroll
                for (int nb = 0; nb < 4; nb++) {
                    uint32_t b0 = smw[bb + boff[nb]];
                    uint32_t b1 = smw[bb + boff[nb] + 4];
                    mma16816(acc[0][nb], a[0][0], a[0][1], a[0][2], a[0][3], b0, b1);
                    mma16816(acc[1][nb], a[1][0], a[1][1], a[1][2], a[1][3], b0, b1);
                }
            }
        }
    }

    // ---- epilogue: out = gate*acc + bias ----
    const float* gr = g_gate + ((size_t)b * HW_ + y) * HW_;
    float* ob = out + (size_t)b * O_ * HW_ * HW_ + (size_t)y * HW_;
    #pragma unroll
    for (int mb = 0; mb < 2; mb++) {
        int px = pxw + mb * 16 + grp;
        float g0 = gr[px], g1 = gr[px + 8];
        #pragma unroll
        for (int nb = 0; nb < 4; nb++) {
            int o = nb * 8 + tig * 2;
            float bi0 = bias_s[o], bi1 = bias_s[o + 1];
            ob[(size_t)o       * (HW_*HW_) + px]     = fmaf(g0, acc[mb][nb][0], bi0);
            ob[(size_t)(o + 1) * (HW_*HW_) + px]     = fmaf(g0, acc[mb][nb][1], bi1);
            ob[(size_t)o       * (HW_*HW_) + px + 8] = fmaf(g1, acc[mb][nb][2], bi0);
            ob[(size_t)(o + 1) * (HW_*HW_) + px + 8] = fmaf(g1, acc[mb][nb][3], bi1);
        }
    }
}

// ================== launch ==================
extern "C" void kernel_launch(void* const* d_in, const int* in_sizes, int n_in,
                              void* d_out, int out_size)
{
    const float* x       = (const float*)d_in[0];
    const float* weight  = (const float*)d_in[1];
    const float* dweight = (const float*)d_in[2];
    const float* bias    = (const float*)d_in[3];
    float* out = (float*)d_out;

    cudaFuncSetAttribute(gate_kernel, cudaFuncAttributeMaxDynamicSharedMemorySize, G_SMEM);
    cudaFuncSetAttribute(conv_kernel, cudaFuncAttributeMaxDynamicSharedMemorySize, SM_TOT_BYTES);

    dim3 g1(HW_ / G_TW, HW_ / G_TH, B_);   // 8 x 16 x 8
    gate_kernel<<<g1, 256, G_SMEM>>>(x, dweight);

    dim3 g2(HW_, B_, 1);                   // 256 rows x 8 batches
    conv_kernel<<<g2, 256, SM_TOT_BYTES>>>(x, weight, bias, out);
}

// round 6
// speedup vs baseline: 1.4929x; 1.4929x over previous
#include <cuda_runtime.h>
#include <cuda_bf16.h>
#include <cstdint>

#define HW_ 256
#define C_  32
#define O_  32
#define B_  8
#define APX 36                       // A words per pixel (32 data + 4 pad)

// smem word offsets
#define SM_BIAS 0
#define SM_DWS  32
#define SM_GS   (SM_DWS + 288)       // 320
#define SM_A    (SM_GS + 256)        // 576  (byte 2304, 16B aligned)
#define SM_B    (SM_A + 3*258*APX)   // 576 + 27864 = 28440
#define SM_TOT_W (SM_B + 9*2*4*384)  // 28440 + 27648 = 56088
#define SM_TOT_BYTES (SM_TOT_W * 4)  // 224352

__device__ __forceinline__ uint32_t smem_u32(const void* p) {
    uint32_t a;
    asm("{ .reg .u64 t; cvta.to.shared.u64 t, %1; cvt.u32.u64 %0, t; }" : "=r"(a) : "l"(p));
    return a;
}

__device__ __forceinline__ uint32_t pack_hilo(float v) {
    __nv_bfloat16 h = __float2bfloat16(v);
    float hf = __bfloat162float(h);
    __nv_bfloat16 l = __float2bfloat16(v - hf);
    return (uint32_t)__bfloat16_as_ushort(h) | ((uint32_t)__bfloat16_as_ushort(l) << 16);
}

// tanh(x/2) where x = hi+lo reconstructed from packed word
__device__ __forceinline__ float tanh_half_pk(uint32_t w) {
    float v = __uint_as_float(w << 16) + __uint_as_float(w & 0xFFFF0000u);
    float t;
    asm("tanh.approx.f32 %0, %1;" : "=f"(t) : "f"(v * 0.5f));
    return t;
}

__device__ __forceinline__ void ldsm4(uint32_t& r0, uint32_t& r1, uint32_t& r2, uint32_t& r3,
                                      uint32_t addr) {
    asm volatile("ldmatrix.sync.aligned.m8n8.x4.shared.b16 {%0,%1,%2,%3}, [%4];"
                 : "=r"(r0), "=r"(r1), "=r"(r2), "=r"(r3) : "r"(addr));
}

__device__ __forceinline__ void mma16816(float* c, uint32_t a0, uint32_t a1,
                                         uint32_t a2, uint32_t a3,
                                         uint32_t b0, uint32_t b1) {
    asm volatile(
        "mma.sync.aligned.m16n8k16.row.col.f32.bf16.bf16.f32 "
        "{%0,%1,%2,%3}, {%4,%5,%6,%7}, {%8,%9}, {%0,%1,%2,%3};"
        : "+f"(c[0]), "+f"(c[1]), "+f"(c[2]), "+f"(c[3])
        : "r"(a0), "r"(a1), "r"(a2), "r"(a3), "r"(b0), "r"(b1));
}

__global__ __launch_bounds__(256, 1)
void dynamiconv_kernel(const float* __restrict__ x, const float* __restrict__ weight,
                       const float* __restrict__ dweight, const float* __restrict__ bias,
                       float* __restrict__ out)
{
    extern __shared__ char smraw[];
    uint32_t* smw   = (uint32_t*)smraw;
    float*    bias_s = (float*)smraw;            // SM_BIAS
    float*    dws_s  = (float*)smraw + SM_DWS;
    float*    gs     = (float*)smraw + SM_GS;

    const int tid  = threadIdx.x;
    const int lane = tid & 31;
    const int warp = tid >> 5;
    const int y = blockIdx.x;
    const int b = blockIdx.y;

    if (tid < 32) bias_s[tid] = bias[tid];
    for (int i = tid; i < 288; i += 256) dws_s[i] = dweight[i];   // FIXED: full 288 loaded

    // ---- A fill: 3 halo rows x 32c x 64 float4-groups (hp = 1..256) ----
    const float* xb = x + (size_t)b * C_ * HW_ * HW_;
    for (int i = tid; i < 3 * 32 * 64; i += 256) {
        int r   = i >> 11;
        int rem = i & 2047;
        int c   = rem >> 6;
        int g4  = rem & 63;
        int gy  = y - 1 + r;
        float4 v = make_float4(0.f, 0.f, 0.f, 0.f);
        if ((unsigned)gy < HW_)
            v = *(const float4*)(xb + (size_t)c * HW_ * HW_ + gy * HW_ + g4 * 4);
        int base = SM_A + (r * 258 + g4 * 4 + 1) * APX + c;
        smw[base]           = pack_hilo(v.x);
        smw[base + APX]     = pack_hilo(v.y);
        smw[base + 2 * APX] = pack_hilo(v.z);
        smw[base + 3 * APX] = pack_hilo(v.w);
    }
    // halo edge columns hp=0 and hp=257 -> zero
    for (int i = tid; i < 3 * 32 * 2; i += 256) {
        int r = i / 64; int rem = i - r * 64; int c = rem >> 1; int e = rem & 1;
        smw[SM_A + (r * 258 + e * 257) * APX + c] = 0;
    }
    // ---- B fill: [tap][set][kch] blocks of 32o x 8kp, o-stride 12 ----
    for (int i = tid; i < O_ * C_ * 9; i += 256) {
        float w  = weight[i];
        int o    = i / 288;
        int rem  = i - o * 288;
        int c    = rem / 9;
        int tap  = rem - c * 9;
        __nv_bfloat16 h = __float2bfloat16(w);
        float hf = __bfloat162float(h);
        __nv_bfloat16 l = __float2bfloat16(w - hf);
        uint32_t hu = __bfloat16_as_ushort(h);
        uint32_t lu = __bfloat16_as_ushort(l);
        int kch = c >> 3, kp = c & 7;
        smw[SM_B + ((tap * 2 + 0) * 4 + kch) * 384 + o * 12 + kp] = hu | (hu << 16);
        smw[SM_B + ((tap * 2 + 1) * 4 + kch) * 384 + o * 12 + kp] = lu;
    }
    __syncthreads();

    // ================= gate pass (lane = channel, conflict-free) =================
    // gate[px] = sum_{c,tap} dw * sigmoid(x) = 0.5*sum(dw) + sum(0.5*dw * tanh(x/2))
    {
        const int c = lane;
        float dwr[9], sd2 = 0.f;
        #pragma unroll
        for (int j = 0; j < 9; j++) { dwr[j] = 0.5f * dws_s[c * 9 + j]; sd2 += dwr[j]; }
        const int pxb = warp * 32;

        float c0[3], c1[3], c2[3];
        #pragma unroll
        for (int r = 0; r < 3; r++) {
            c0[r] = tanh_half_pk(smw[SM_A + (r * 258 + pxb)     * APX + c]);
            c1[r] = tanh_half_pk(smw[SM_A + (r * 258 + pxb + 1) * APX + c]);
        }
        float part[8];
        #pragma unroll
        for (int px = 0; px < 32; px++) {
            #pragma unroll
            for (int r = 0; r < 3; r++)
                c2[r] = tanh_half_pk(smw[SM_A + (r * 258 + pxb + px + 2) * APX + c]);
            float p = sd2;
            #pragma unroll
            for (int r = 0; r < 3; r++) {
                p = fmaf(dwr[r * 3 + 0], c0[r], p);
                p = fmaf(dwr[r * 3 + 1], c1[r], p);
                p = fmaf(dwr[r * 3 + 2], c2[r], p);
            }
            part[px & 7] = p;
            if ((px & 7) == 7) {
                int base = pxb + (px & ~7);
                #pragma unroll
                for (int j = 0; j < 8; j++) {
                    float v = part[j];
                    v += __shfl_xor_sync(0xFFFFFFFFu, v, 16);
                    v += __shfl_xor_sync(0xFFFFFFFFu, v, 8);
                    v += __shfl_xor_sync(0xFFFFFFFFu, v, 4);
                    v += __shfl_xor_sync(0xFFFFFFFFu, v, 2);
                    v += __shfl_xor_sync(0xFFFFFFFFu, v, 1);
                    if (lane == j) gs[base + j] = v;
                }
            }
            #pragma unroll
            for (int r = 0; r < 3; r++) { c0[r] = c1[r]; c1[r] = c2[r]; }
        }
    }
    __syncthreads();

    // ================= mainloop: ldmatrix + mma =================
    const uint32_t sbase = smem_u32(smraw);
    const uint32_t Abase = sbase + SM_A * 4;
    const uint32_t Bbase = sbase + SM_B * 4;
    // A lane part: matrix m = lane>>3 -> pxoff = (m&1)*8 + row, kword = (m>>1)*4
    const uint32_t laneA = ((((lane >> 3) & 1) * 8 + (lane & 7)) * APX + (lane >> 4) * 4) * 4;
    // B lane part: matrices (o0-7 w0-3),(o0-7 w4-7),(o8-15 w0-3),(o8-15 w4-7)
    const uint32_t laneB = ((((lane >> 4) & 1) * 8 + (lane & 7)) * 12 + ((lane >> 3) & 1) * 4) * 4;

    float acc[2][4][4];
    #pragma unroll
    for (int mb = 0; mb < 2; mb++)
        #pragma unroll
        for (int nb = 0; nb < 4; nb++)
            #pragma unroll
            for (int r = 0; r < 4; r++) acc[mb][nb][r] = 0.0f;

    const int pxw = warp * 32;

    #pragma unroll 1
    for (int ki = 0; ki < 3; ki++) {
        #pragma unroll 1
        for (int kj = 0; kj < 3; kj++) {
            uint32_t aaddr = Abase + (uint32_t)((ki * 258 + pxw + kj) * APX * 4) + laneA;
            uint32_t baddr = Bbase + (uint32_t)((ki * 3 + kj) * 12288) + laneB;
            #pragma unroll
            for (int kch = 0; kch < 4; kch++) {
                uint32_t a[8];
                ldsm4(a[0], a[1], a[2], a[3], aaddr + kch * 32);
                ldsm4(a[4], a[5], a[6], a[7], aaddr + 16 * APX * 4 + kch * 32);
                #pragma unroll
                for (int set = 0; set < 2; set++) {
                    uint32_t bq[8];
                    uint32_t bs_ = baddr + (uint32_t)(set * 6144 + kch * 1536);
                    ldsm4(bq[0], bq[1], bq[2], bq[3], bs_);         // o0-7 (b0,b1), o8-15 (b0,b1)
                    ldsm4(bq[4], bq[5], bq[6], bq[7], bs_ + 768);   // o16-23, o24-31
                    #pragma unroll
                    for (int mb = 0; mb < 2; mb++) {
                        mma16816(acc[mb][0], a[mb*4+0], a[mb*4+1], a[mb*4+2], a[mb*4+3], bq[0], bq[1]);
                        mma16816(acc[mb][1], a[mb*4+0], a[mb*4+1], a[mb*4+2], a[mb*4+3], bq[2], bq[3]);
                        mma16816(acc[mb][2], a[mb*4+0], a[mb*4+1], a[mb*4+2], a[mb*4+3], bq[4], bq[5]);
                        mma16816(acc[mb][3], a[mb*4+0], a[mb*4+1], a[mb*4+2], a[mb*4+3], bq[6], bq[7]);
                    }
                }
            }
        }
    }

    // ================= epilogue: out = gate*acc + bias =================
    const int tig = lane & 3, grp = lane >> 2;
    float* ob = out + (size_t)b * O_ * HW_ * HW_ + (size_t)y * HW_;
    #pragma unroll
    for (int mb = 0; mb < 2; mb++) {
        int px = pxw + mb * 16 + grp;
        float g0 = gs[px], g1 = gs[px + 8];
        #pragma unroll
        for (int nb = 0; nb < 4; nb++) {
            int o = nb * 8 + tig * 2;
            float bi0 = bias_s[o], bi1 = bias_s[o + 1];
            ob[(size_t)o       * (HW_*HW_) + px]     = fmaf(g0, acc[mb][nb][0], bi0);
            ob[(size_t)(o + 1) * (HW_*HW_) + px]     = fmaf(g0, acc[mb][nb][1], bi1);
            ob[(size_t)o       * (HW_*HW_) + px + 8] = fmaf(g1, acc[mb][nb][2], bi0);
            ob[(size_t)(o + 1) * (HW_*HW_) + px + 8] = fmaf(g1, acc[mb][nb][3], bi1);
        }
    }
}

extern "C" void kernel_launch(void* const* d_in, const int* in_sizes, int n_in,
                              void* d_out, int out_size)
{
    const float* x       = (const float*)d_in[0];
    const float* weight  = (const float*)d_in[1];
    const float* dweight = (const float*)d_in[2];
    const float* bias    = (const float*)d_in[3];
    float* out = (float*)d_out;

    cudaFuncSetAttribute(dynamiconv_kernel,
                         cudaFuncAttributeMaxDynamicSharedMemorySize, SM_TOT_BYTES);

    dim3 grid(HW_, B_, 1);   // 256 rows x 8 batches = 2048 CTAs
    dynamiconv_kernel<<<grid, 256, SM_TOT_BYTES>>>(x, weight, dweight, bias, out);
}

// round 7
// speedup vs baseline: 1.9650x; 1.3162x over previous
#include <cuda_runtime.h>
#include <cuda_bf16.h>
#include <cstdint>

#define HW_ 256
#define C_  32
#define O_  32
#define B_  8
#define APX 36                       // A words per pixel (32 data + 4 pad)

// smem word offsets
#define SM_BIAS 0
#define SM_DWS  32
#define SM_GS   (SM_DWS + 288)       // 320
#define SM_A    (SM_GS + 256)        // 576  (byte 2304, 16B aligned)
#define SM_B    (SM_A + 3*258*APX)   // 28440
#define SM_TOT_W (SM_B + 9*2*4*384)  // 56088
#define SM_TOT_BYTES (SM_TOT_W * 4)  // 224352

__device__ __forceinline__ uint32_t smem_u32(const void* p) {
    uint32_t a;
    asm("{ .reg .u64 t; cvta.to.shared.u64 t, %1; cvt.u32.u64 %0, t; }" : "=r"(a) : "l"(p));
    return a;
}

__device__ __forceinline__ uint32_t pack_hilo(float v) {
    __nv_bfloat16 h = __float2bfloat16(v);
    float hf = __bfloat162float(h);
    __nv_bfloat16 l = __float2bfloat16(v - hf);
    return (uint32_t)__bfloat16_as_ushort(h) | ((uint32_t)__bfloat16_as_ushort(l) << 16);
}

// tanh(x/2) where x = hi+lo reconstructed from packed word
__device__ __forceinline__ float tanh_half_pk(uint32_t w) {
    float v = __uint_as_float(w << 16) + __uint_as_float(w & 0xFFFF0000u);
    float t;
    asm("tanh.approx.f32 %0, %1;" : "=f"(t) : "f"(v * 0.5f));
    return t;
}

__device__ __forceinline__ void ldsm4(uint32_t& r0, uint32_t& r1, uint32_t& r2, uint32_t& r3,
                                      uint32_t addr) {
    asm volatile("ldmatrix.sync.aligned.m8n8.x4.shared.b16 {%0,%1,%2,%3}, [%4];"
                 : "=r"(r0), "=r"(r1), "=r"(r2), "=r"(r3) : "r"(addr));
}

__device__ __forceinline__ void mma16816(float* c, uint32_t a0, uint32_t a1,
                                         uint32_t a2, uint32_t a3,
                                         uint32_t b0, uint32_t b1) {
    asm volatile(
        "mma.sync.aligned.m16n8k16.row.col.f32.bf16.bf16.f32 "
        "{%0,%1,%2,%3}, {%4,%5,%6,%7}, {%8,%9}, {%0,%1,%2,%3};"
        : "+f"(c[0]), "+f"(c[1]), "+f"(c[2]), "+f"(c[3])
        : "r"(a0), "r"(a1), "r"(a2), "r"(a3), "r"(b0), "r"(b1));
}

__global__ __launch_bounds__(256, 1)
void dynamiconv_kernel(const float* __restrict__ x, const float* __restrict__ weight,
                       const float* __restrict__ dweight, const float* __restrict__ bias,
                       float* __restrict__ out)
{
    extern __shared__ char smraw[];
    uint32_t* smw   = (uint32_t*)smraw;
    float*    bias_s = (float*)smraw;            // SM_BIAS
    float*    dws_s  = (float*)smraw + SM_DWS;
    float*    gs     = (float*)smraw + SM_GS;

    const int tid  = threadIdx.x;
    const int lane = tid & 31;
    const int warp = tid >> 5;
    const int y = blockIdx.x;
    const int b = blockIdx.y;

    if (tid < 32) bias_s[tid] = bias[tid];
    for (int i = tid; i < 288; i += 256) dws_s[i] = dweight[i];

    // ---- A fill: thread = pixel (hp = tid+1), 32 channels each; STS.128 conflict-free ----
    const float* xb = x + (size_t)b * C_ * HW_ * HW_;
    {
        const int gx = tid;                // gx 0..255 <-> hp = tid+1
        #pragma unroll
        for (int r = 0; r < 3; r++) {
            int gy = y - 1 + r;
            bool inb = ((unsigned)gy < (unsigned)HW_);
            const float* src = xb + (size_t)gy * HW_ + gx;
            uint32_t* dst = smw + SM_A + (r * 258 + tid + 1) * APX;
            #pragma unroll
            for (int q = 0; q < 8; q++) {
                float v0 = 0.f, v1 = 0.f, v2 = 0.f, v3 = 0.f;
                if (inb) {
                    v0 = src[(size_t)(4*q + 0) * (HW_*HW_)];
                    v1 = src[(size_t)(4*q + 1) * (HW_*HW_)];
                    v2 = src[(size_t)(4*q + 2) * (HW_*HW_)];
                    v3 = src[(size_t)(4*q + 3) * (HW_*HW_)];
                }
                uint4 w = make_uint4(pack_hilo(v0), pack_hilo(v1), pack_hilo(v2), pack_hilo(v3));
                *(uint4*)(dst + 4*q) = w;
            }
        }
        // halo edge columns hp=0 and hp=257 -> zero (48 STS.128)
        if (tid < 48) {
            int r = tid >> 4, rem = tid & 15, e = rem >> 3, q = rem & 7;
            *(uint4*)(smw + SM_A + (r * 258 + e * 257) * APX + 4*q) = make_uint4(0,0,0,0);
        }
    }
    // ---- B fill: [tap][set][kch] blocks of 32o x 8kp, o-stride 12 ----
    for (int i = tid; i < O_ * C_ * 9; i += 256) {
        float w  = weight[i];
        int o    = i / 288;
        int rem  = i - o * 288;
        int c    = rem / 9;
        int tap  = rem - c * 9;
        __nv_bfloat16 h = __float2bfloat16(w);
        float hf = __bfloat162float(h);
        __nv_bfloat16 l = __float2bfloat16(w - hf);
        uint32_t hu = __bfloat16_as_ushort(h);
        uint32_t lu = __bfloat16_as_ushort(l);
        int kch = c >> 3, kp = c & 7;
        smw[SM_B + ((tap * 2 + 0) * 4 + kch) * 384 + o * 12 + kp] = hu | (hu << 16);
        smw[SM_B + ((tap * 2 + 1) * 4 + kch) * 384 + o * 12 + kp] = lu;
    }
    __syncthreads();

    // ================= gate pass (lane = channel, conflict-free) =================
    {
        const int c = lane;
        float dwr[9], sd2 = 0.f;
        #pragma unroll
        for (int j = 0; j < 9; j++) { dwr[j] = 0.5f * dws_s[c * 9 + j]; sd2 += dwr[j]; }
        const int pxb = warp * 32;

        float c0[3], c1[3], c2[3];
        #pragma unroll
        for (int r = 0; r < 3; r++) {
            c0[r] = tanh_half_pk(smw[SM_A + (r * 258 + pxb)     * APX + c]);
            c1[r] = tanh_half_pk(smw[SM_A + (r * 258 + pxb + 1) * APX + c]);
        }
        float part[8];
        #pragma unroll
        for (int px = 0; px < 32; px++) {
            #pragma unroll
            for (int r = 0; r < 3; r++)
                c2[r] = tanh_half_pk(smw[SM_A + (r * 258 + pxb + px + 2) * APX + c]);
            float p = sd2;
            #pragma unroll
            for (int r = 0; r < 3; r++) {
                p = fmaf(dwr[r * 3 + 0], c0[r], p);
                p = fmaf(dwr[r * 3 + 1], c1[r], p);
                p = fmaf(dwr[r * 3 + 2], c2[r], p);
            }
            part[px & 7] = p;
            if ((px & 7) == 7) {
                int base = pxb + (px & ~7);
                #pragma unroll
                for (int j = 0; j < 8; j++) {
                    float v = part[j];
                    v += __shfl_xor_sync(0xFFFFFFFFu, v, 16);
                    v += __shfl_xor_sync(0xFFFFFFFFu, v, 8);
                    v += __shfl_xor_sync(0xFFFFFFFFu, v, 4);
                    v += __shfl_xor_sync(0xFFFFFFFFu, v, 2);
                    v += __shfl_xor_sync(0xFFFFFFFFu, v, 1);
                    if (lane == j) gs[base + j] = v;
                }
            }
            #pragma unroll
            for (int r = 0; r < 3; r++) { c0[r] = c1[r]; c1[r] = c2[r]; }
        }
    }
    __syncthreads();

    // ================= mainloop: ldmatrix + mma =================
    const uint32_t sbase = smem_u32(smraw);
    const uint32_t Abase = sbase + SM_A * 4;
    const uint32_t Bbase = sbase + SM_B * 4;
    const uint32_t laneA = ((((lane >> 3) & 1) * 8 + (lane & 7)) * APX + (lane >> 4) * 4) * 4;
    const uint32_t laneB = ((((lane >> 4) & 1) * 8 + (lane & 7)) * 12 + ((lane >> 3) & 1) * 4) * 4;

    float acc[2][4][4];
    #pragma unroll
    for (int mb = 0; mb < 2; mb++)
        #pragma unroll
        for (int nb = 0; nb < 4; nb++)
            #pragma unroll
            for (int r = 0; r < 4; r++) acc[mb][nb][r] = 0.0f;

    const int pxw = warp * 32;

    #pragma unroll 1
    for (int ki = 0; ki < 3; ki++) {
        #pragma unroll 1
        for (int kj = 0; kj < 3; kj++) {
            uint32_t aaddr = Abase + (uint32_t)((ki * 258 + pxw + kj) * APX * 4) + laneA;
            uint32_t baddr = Bbase + (uint32_t)((ki * 3 + kj) * 12288) + laneB;
            #pragma unroll
            for (int kch = 0; kch < 4; kch++) {
                uint32_t a[8];
                ldsm4(a[0], a[1], a[2], a[3], aaddr + kch * 32);
                ldsm4(a[4], a[5], a[6], a[7], aaddr + 16 * APX * 4 + kch * 32);
                #pragma unroll
                for (int set = 0; set < 2; set++) {
                    uint32_t bq[8];
                    uint32_t bs_ = baddr + (uint32_t)(set * 6144 + kch * 1536);
                    ldsm4(bq[0], bq[1], bq[2], bq[3], bs_);
                    ldsm4(bq[4], bq[5], bq[6], bq[7], bs_ + 768);
                    #pragma unroll
                    for (int mb = 0; mb < 2; mb++) {
                        mma16816(acc[mb][0], a[mb*4+0], a[mb*4+1], a[mb*4+2], a[mb*4+3], bq[0], bq[1]);
                        mma16816(acc[mb][1], a[mb*4+0], a[mb*4+1], a[mb*4+2], a[mb*4+3], bq[2], bq[3]);
                        mma16816(acc[mb][2], a[mb*4+0], a[mb*4+1], a[mb*4+2], a[mb*4+3], bq[4], bq[5]);
                        mma16816(acc[mb][3], a[mb*4+0], a[mb*4+1], a[mb*4+2], a[mb*4+3], bq[6], bq[7]);
                    }
                }
            }
        }
    }

    // ================= epilogue: out = gate*acc + bias =================
    const int tig = lane & 3, grp = lane >> 2;
    float* ob = out + (size_t)b * O_ * HW_ * HW_ + (size_t)y * HW_;
    #pragma unroll
    for (int mb = 0; mb < 2; mb++) {
        int px = pxw + mb * 16 + grp;
        float g0 = gs[px], g1 = gs[px + 8];
        #pragma unroll
        for (int nb = 0; nb < 4; nb++) {
            int o = nb * 8 + tig * 2;
            float bi0 = bias_s[o], bi1 = bias_s[o + 1];
            ob[(size_t)o       * (HW_*HW_) + px]     = fmaf(g0, acc[mb][nb][0], bi0);
            ob[(size_t)(o + 1) * (HW_*HW_) + px]     = fmaf(g0, acc[mb][nb][1], bi1);
            ob[(size_t)o       * (HW_*HW_) + px + 8] = fmaf(g1, acc[mb][nb][2], bi0);
            ob[(size_t)(o + 1) * (HW_*HW_) + px + 8] = fmaf(g1, acc[mb][nb][3], bi1);
        }
    }
}

extern "C" void kernel_launch(void* const* d_in, const int* in_sizes, int n_in,
                              void* d_out, int out_size)
{
    const float* x       = (const float*)d_in[0];
    const float* weight  = (const float*)d_in[1];
    const float* dweight = (const float*)d_in[2];
    const float* bias    = (const float*)d_in[3];
    float* out = (float*)d_out;

    cudaFuncSetAttribute(dynamiconv_kernel,
                         cudaFuncAttributeMaxDynamicSharedMemorySize, SM_TOT_BYTES);

    dim3 grid(HW_, B_, 1);   // 256 rows x 8 batches = 2048 CTAs
    dynamiconv_kernel<<<grid, 256, SM_TOT_BYTES>>>(x, weight, dweight, bias, out);
}

// round 8
// speedup vs baseline: 4.3119x; 2.1944x over previous
#include <cuda_runtime.h>
#include <cuda_fp16.h>
#include <cstdint>

#define HW_ 256
#define C_  32
#define O_  32
#define B_  8
#define APX 20                       // A words per pixel (16 fp16x2 + 4 pad)

// smem word offsets
#define SM_BIAS 0
#define SM_DWS  32
#define SM_GS   (SM_DWS + 288)       // 320
#define SM_A    (SM_GS + 256)        // 576
#define SM_B    (SM_A + 3*258*APX)   // 576 + 15480 = 16056
#define SM_TOT_W (SM_B + 9*2*384)    // 16056 + 6912 = 22968
#define SM_TOT_BYTES (SM_TOT_W * 4)  // 91872 bytes -> 2 CTAs/SM

__device__ __forceinline__ uint32_t smem_u32(const void* p) {
    uint32_t a;
    asm("{ .reg .u64 t; cvta.to.shared.u64 t, %1; cvt.u32.u64 %0, t; }" : "=r"(a) : "l"(p));
    return a;
}

__device__ __forceinline__ uint32_t pk2h(float a, float b) {
    __half2 h = __floats2half2_rn(a, b);
    return *reinterpret_cast<uint32_t*>(&h);
}

__device__ __forceinline__ void ldsm4(uint32_t& r0, uint32_t& r1, uint32_t& r2, uint32_t& r3,
                                      uint32_t addr) {
    asm volatile("ldmatrix.sync.aligned.m8n8.x4.shared.b16 {%0,%1,%2,%3}, [%4];"
                 : "=r"(r0), "=r"(r1), "=r"(r2), "=r"(r3) : "r"(addr));
}

__device__ __forceinline__ void mma16816(float* c, uint32_t a0, uint32_t a1,
                                         uint32_t a2, uint32_t a3,
                                         uint32_t b0, uint32_t b1) {
    asm volatile(
        "mma.sync.aligned.m16n8k16.row.col.f32.f16.f16.f32 "
        "{%0,%1,%2,%3}, {%4,%5,%6,%7}, {%8,%9}, {%0,%1,%2,%3};"
        : "+f"(c[0]), "+f"(c[1]), "+f"(c[2]), "+f"(c[3])
        : "r"(a0), "r"(a1), "r"(a2), "r"(a3), "r"(b0), "r"(b1));
}

__global__ __launch_bounds__(256, 2)
void dynamiconv_kernel(const float* __restrict__ x, const float* __restrict__ weight,
                       const float* __restrict__ dweight, const float* __restrict__ bias,
                       float* __restrict__ out)
{
    extern __shared__ char smraw[];
    uint32_t* smw    = (uint32_t*)smraw;
    float*    bias_s = (float*)smraw;            // SM_BIAS
    float*    dws_s  = (float*)smraw + SM_DWS;
    float*    gs     = (float*)smraw + SM_GS;

    const int tid  = threadIdx.x;
    const int lane = tid & 31;
    const int warp = tid >> 5;
    const int y = blockIdx.x;
    const int b = blockIdx.y;

    if (tid < 32) bias_s[tid] = bias[tid];
    for (int i = tid; i < 288; i += 256) dws_s[i] = dweight[i];

    // ---- A fill: thread = pixel (hp = tid+1); word kw = fp16x2(ch 2kw, 2kw+1) ----
    const float* xb = x + (size_t)b * C_ * HW_ * HW_;
    {
        const int gx = tid;
        #pragma unroll
        for (int r = 0; r < 3; r++) {
            int gy = y - 1 + r;
            bool inb = ((unsigned)gy < (unsigned)HW_);
            const float* src = xb + (size_t)gy * HW_ + gx;
            uint32_t* dst = smw + SM_A + (r * 258 + tid + 1) * APX;
            #pragma unroll
            for (int q = 0; q < 4; q++) {
                float v[8];
                #pragma unroll
                for (int j = 0; j < 8; j++)
                    v[j] = inb ? src[(size_t)(8*q + j) * (HW_*HW_)] : 0.f;
                uint4 w = make_uint4(pk2h(v[0], v[1]), pk2h(v[2], v[3]),
                                     pk2h(v[4], v[5]), pk2h(v[6], v[7]));
                *(uint4*)(dst + 4*q) = w;
            }
        }
        // halo edge columns hp=0 and hp=257 -> zero (24 STS.128)
        if (tid < 24) {
            int r = tid >> 3, rem = tid & 7, e = rem >> 2, q = rem & 3;
            *(uint4*)(smw + SM_A + (r * 258 + e * 257) * APX + 4*q) = make_uint4(0,0,0,0);
        }
    }
    // ---- B fill: [tap][kch] blocks of 32o x 8 words (16 fp16 k), o-stride 12 ----
    for (int i = tid; i < O_ * 9 * 16; i += 256) {
        int o   = i / 144;
        int rem = i - o * 144;
        int tap = rem / 16;
        int kpg = rem - tap * 16;        // word index 0..15 -> channels 2kpg, 2kpg+1
        int c0  = kpg * 2;
        float w0 = weight[o * 288 + c0 * 9 + tap];
        float w1 = weight[o * 288 + (c0 + 1) * 9 + tap];
        int kch = kpg >> 3, kp = kpg & 7;
        smw[SM_B + (tap * 2 + kch) * 384 + o * 12 + kp] = pk2h(w0, w1);
    }
    __syncthreads();

    // ================= gate pass (lane = channel; fp16 broadcast reads) =================
    {
        const int c = lane;
        const int sh = (lane & 1) * 16;
        float dwr[9], sd2 = 0.f;
        #pragma unroll
        for (int j = 0; j < 9; j++) { dwr[j] = 0.5f * dws_s[c * 9 + j]; sd2 += dwr[j]; }
        const int pxb = warp * 32;

        float c0[3], c1[3], c2[3];
        #pragma unroll
        for (int r = 0; r < 3; r++) {
            uint32_t w0 = smw[SM_A + (r * 258 + pxb)     * APX + (c >> 1)];
            uint32_t w1 = smw[SM_A + (r * 258 + pxb + 1) * APX + (c >> 1)];
            float v0 = __half2float(__ushort_as_half((unsigned short)(w0 >> sh)));
            float v1 = __half2float(__ushort_as_half((unsigned short)(w1 >> sh)));
            asm("tanh.approx.f32 %0, %1;" : "=f"(c0[r]) : "f"(v0 * 0.5f));
            asm("tanh.approx.f32 %0, %1;" : "=f"(c1[r]) : "f"(v1 * 0.5f));
        }
        float part[8];
        #pragma unroll
        for (int px = 0; px < 32; px++) {
            #pragma unroll
            for (int r = 0; r < 3; r++) {
                uint32_t w = smw[SM_A + (r * 258 + pxb + px + 2) * APX + (c >> 1)];
                float v = __half2float(__ushort_as_half((unsigned short)(w >> sh)));
                asm("tanh.approx.f32 %0, %1;" : "=f"(c2[r]) : "f"(v * 0.5f));
            }
            float p = sd2;
            #pragma unroll
            for (int r = 0; r < 3; r++) {
                p = fmaf(dwr[r * 3 + 0], c0[r], p);
                p = fmaf(dwr[r * 3 + 1], c1[r], p);
                p = fmaf(dwr[r * 3 + 2], c2[r], p);
            }
            part[px & 7] = p;
            if ((px & 7) == 7) {
                int base = pxb + (px & ~7);
                #pragma unroll
                for (int j = 0; j < 8; j++) {
                    float v = part[j];
                    v += __shfl_xor_sync(0xFFFFFFFFu, v, 16);
                    v += __shfl_xor_sync(0xFFFFFFFFu, v, 8);
                    v += __shfl_xor_sync(0xFFFFFFFFu, v, 4);
                    v += __shfl_xor_sync(0xFFFFFFFFu, v, 2);
                    v += __shfl_xor_sync(0xFFFFFFFFu, v, 1);
                    if (lane == j) gs[base + j] = v;
                }
            }
            #pragma unroll
            for (int r = 0; r < 3; r++) { c0[r] = c1[r]; c1[r] = c2[r]; }
        }
    }
    __syncthreads();

    // ================= mainloop: ldmatrix + mma (fp16, single set) =================
    const uint32_t sbase = smem_u32(smraw);
    const uint32_t Abase = sbase + SM_A * 4;
    const uint32_t Bbase = sbase + SM_B * 4;
    const uint32_t laneA = ((((lane >> 3) & 1) * 8 + (lane & 7)) * APX + (lane >> 4) * 4) * 4;
    const uint32_t laneB = ((((lane >> 4) & 1) * 8 + (lane & 7)) * 12 + ((lane >> 3) & 1) * 4) * 4;

    float acc[2][4][4];
    #pragma unroll
    for (int mb = 0; mb < 2; mb++)
        #pragma unroll
        for (int nb = 0; nb < 4; nb++)
            #pragma unroll
            for (int r = 0; r < 4; r++) acc[mb][nb][r] = 0.0f;

    const int pxw = warp * 32;

    #pragma unroll 1
    for (int ki = 0; ki < 3; ki++) {
        #pragma unroll 1
        for (int kj = 0; kj < 3; kj++) {
            uint32_t aaddr = Abase + (uint32_t)((ki * 258 + pxw + kj) * APX * 4) + laneA;
            uint32_t baddr = Bbase + (uint32_t)((ki * 3 + kj) * 3072) + laneB;
            // load both kch stages first (batch LDSM), then MMA both
            uint32_t a0[8], a1[8], b0q[8], b1q[8];
            ldsm4(a0[0], a0[1], a0[2], a0[3], aaddr);
            ldsm4(a0[4], a0[5], a0[6], a0[7], aaddr + 16 * APX * 4);
            ldsm4(b0q[0], b0q[1], b0q[2], b0q[3], baddr);
            ldsm4(b0q[4], b0q[5], b0q[6], b0q[7], baddr + 768);
            ldsm4(a1[0], a1[1], a1[2], a1[3], aaddr + 32);
            ldsm4(a1[4], a1[5], a1[6], a1[7], aaddr + 16 * APX * 4 + 32);
            ldsm4(b1q[0], b1q[1], b1q[2], b1q[3], baddr + 1536);
            ldsm4(b1q[4], b1q[5], b1q[6], b1q[7], baddr + 1536 + 768);
            #pragma unroll
            for (int mb = 0; mb < 2; mb++) {
                #pragma unroll
                for (int nb = 0; nb < 4; nb++)
                    mma16816(acc[mb][nb], a0[mb*4+0], a0[mb*4+1], a0[mb*4+2], a0[mb*4+3],
                             b0q[2*nb], b0q[2*nb+1]);
                #pragma unroll
                for (int nb = 0; nb < 4; nb++)
                    mma16816(acc[mb][nb], a1[mb*4+0], a1[mb*4+1], a1[mb*4+2], a1[mb*4+3],
                             b1q[2*nb], b1q[2*nb+1]);
            }
        }
    }

    // ================= epilogue: out = gate*acc + bias =================
    const int tig = lane & 3, grp = lane >> 2;
    float* ob = out + (size_t)b * O_ * HW_ * HW_ + (size_t)y * HW_;
    #pragma unroll
    for (int mb = 0; mb < 2; mb++) {
        int px = pxw + mb * 16 + grp;
        float g0 = gs[px], g1 = gs[px + 8];
        #pragma unroll
        for (int nb = 0; nb < 4; nb++) {
            int o = nb * 8 + tig * 2;
            float bi0 = bias_s[o], bi1 = bias_s[o + 1];
            ob[(size_t)o       * (HW_*HW_) + px]     = fmaf(g0, acc[mb][nb][0], bi0);
            ob[(size_t)(o + 1) * (HW_*HW_) + px]     = fmaf(g0, acc[mb][nb][1], bi1);
            ob[(size_t)o       * (HW_*HW_) + px + 8] = fmaf(g1, acc[mb][nb][2], bi0);
            ob[(size_t)(o + 1) * (HW_*HW_) + px + 8] = fmaf(g1, acc[mb][nb][3], bi1);
        }
    }
}

extern "C" void kernel_launch(void* const* d_in, const int* in_sizes, int n_in,
                              void* d_out, int out_size)
{
    const float* x       = (const float*)d_in[0];
    const float* weight  = (const float*)d_in[1];
    const float* dweight = (const float*)d_in[2];
    const float* bias    = (const float*)d_in[3];
    float* out = (float*)d_out;

    cudaFuncSetAttribute(dynamiconv_kernel,
                         cudaFuncAttributeMaxDynamicSharedMemorySize, SM_TOT_BYTES);

    dim3 grid(HW_, B_, 1);   // 256 rows x 8 batches = 2048 CTAs
    dynamiconv_kernel<<<grid, 256, SM_TOT_BYTES>>>(x, weight, dweight, bias, out);
}

// round 9
// speedup vs baseline: 5.4684x; 1.2682x over previous
#include <cuda_runtime.h>
#include <cuda_fp16.h>
#include <cstdint>

#define HW_ 256
#define C_  32
#define O_  32
#define B_  8
#define APX 20                       // A words per pixel (16 fp16x2 + 4 pad)

// smem word offsets
#define SM_BIAS 0
#define SM_DWS  32
#define SM_GS   (SM_DWS + 288)       // 320
#define SM_A    (SM_GS + 256)        // 576
#define SM_B    (SM_A + 3*258*APX)   // 16056
#define SM_TOT_W (SM_B + 9*2*384)    // 22968
#define SM_TOT_BYTES (SM_TOT_W * 4)  // 91872 bytes -> 2 CTAs/SM

__device__ __forceinline__ uint32_t smem_u32(const void* p) {
    uint32_t a;
    asm("{ .reg .u64 t; cvta.to.shared.u64 t, %1; cvt.u32.u64 %0, t; }" : "=r"(a) : "l"(p));
    return a;
}

__device__ __forceinline__ uint32_t pk2h(float a, float b) {
    __half2 h = __floats2half2_rn(a, b);
    return *reinterpret_cast<uint32_t*>(&h);
}

__device__ __forceinline__ void ldsm4(uint32_t& r0, uint32_t& r1, uint32_t& r2, uint32_t& r3,
                                      uint32_t addr) {
    asm volatile("ldmatrix.sync.aligned.m8n8.x4.shared.b16 {%0,%1,%2,%3}, [%4];"
                 : "=r"(r0), "=r"(r1), "=r"(r2), "=r"(r3) : "r"(addr));
}

__device__ __forceinline__ void mma16816(float* c, uint32_t a0, uint32_t a1,
                                         uint32_t a2, uint32_t a3,
                                         uint32_t b0, uint32_t b1) {
    asm volatile(
        "mma.sync.aligned.m16n8k16.row.col.f32.f16.f16.f32 "
        "{%0,%1,%2,%3}, {%4,%5,%6,%7}, {%8,%9}, {%0,%1,%2,%3};"
        : "+f"(c[0]), "+f"(c[1]), "+f"(c[2]), "+f"(c[3])
        : "r"(a0), "r"(a1), "r"(a2), "r"(a3), "r"(b0), "r"(b1));
}

__global__ __launch_bounds__(256, 2)
void dynamiconv_kernel(const float* __restrict__ x, const float* __restrict__ weight,
                       const float* __restrict__ dweight, const float* __restrict__ bias,
                       float* __restrict__ out)
{
    extern __shared__ char smraw[];
    uint32_t* smw    = (uint32_t*)smraw;
    float*    bias_s = (float*)smraw;            // SM_BIAS
    float*    dws_s  = (float*)smraw + SM_DWS;
    float*    gs     = (float*)smraw + SM_GS;

    const int tid  = threadIdx.x;
    const int lane = tid & 31;
    const int warp = tid >> 5;
    const int y = blockIdx.x;
    const int b = blockIdx.y;

    if (tid < 32) bias_s[tid] = bias[tid];
    for (int i = tid; i < 288; i += 256) dws_s[i] = dweight[i];

    // ---- B fill: thread t owns contiguous 36-float chunk (one o, 4 channels, 9 taps) ----
    {
        float wchunk[36];
        const float4* ws4 = (const float4*)(weight + tid * 36);
        #pragma unroll
        for (int j = 0; j < 9; j++) ((float4*)wchunk)[j] = ws4[j];
        const int o    = tid >> 3;
        const int kpg0 = (tid & 7) * 2;        // even, 0..14
        const int kch0 = kpg0 >> 3, kp0 = kpg0 & 7;
        const int kpg1 = kpg0 + 1;
        const int kch1 = kpg1 >> 3, kp1 = kpg1 & 7;
        #pragma unroll
        for (int tap = 0; tap < 9; tap++) {
            smw[SM_B + (tap*2 + kch0)*384 + o*12 + kp0] = pk2h(wchunk[tap],      wchunk[tap + 9]);
            smw[SM_B + (tap*2 + kch1)*384 + o*12 + kp1] = pk2h(wchunk[tap + 18], wchunk[tap + 27]);
        }
    }

    // ---- A fill: thread = pixel (hp = tid+1); word kw = fp16x2(ch 2kw, 2kw+1) ----
    const float* xb = x + (size_t)b * C_ * HW_ * HW_;
    {
        const int gx = tid;
        #pragma unroll
        for (int r = 0; r < 3; r++) {
            int gy = y - 1 + r;
            bool inb = ((unsigned)gy < (unsigned)HW_);
            const float* src = xb + (size_t)gy * HW_ + gx;
            uint32_t* dst = smw + SM_A + (r * 258 + tid + 1) * APX;
            #pragma unroll
            for (int q = 0; q < 4; q++) {
                float v[8];
                #pragma unroll
                for (int j = 0; j < 8; j++)
                    v[j] = inb ? src[(size_t)(8*q + j) * (HW_*HW_)] : 0.f;
                uint4 w = make_uint4(pk2h(v[0], v[1]), pk2h(v[2], v[3]),
                                     pk2h(v[4], v[5]), pk2h(v[6], v[7]));
                *(uint4*)(dst + 4*q) = w;
            }
        }
        if (tid < 24) {
            int r = tid >> 3, rem = tid & 7, e = rem >> 2, q = rem & 3;
            *(uint4*)(smw + SM_A + (r * 258 + e * 257) * APX + 4*q) = make_uint4(0,0,0,0);
        }
    }
    __syncthreads();

    // ================= gate pass (lane = channel; transpose-reduce) =================
    {
        const int c = lane;
        const int sh = (lane & 1) * 16;
        float dwr[9], sd2 = 0.f;
        #pragma unroll
        for (int j = 0; j < 9; j++) { dwr[j] = 0.5f * dws_s[c * 9 + j]; sd2 += dwr[j]; }
        const int pxb = warp * 32;

        float c0[3], c1[3];
        #pragma unroll
        for (int r = 0; r < 3; r++) {
            uint32_t w0 = smw[SM_A + (r * 258 + pxb)     * APX + (c >> 1)];
            uint32_t w1 = smw[SM_A + (r * 258 + pxb + 1) * APX + (c >> 1)];
            float v0 = __half2float(__ushort_as_half((unsigned short)(w0 >> sh)));
            float v1 = __half2float(__ushort_as_half((unsigned short)(w1 >> sh)));
            asm("tanh.approx.f32 %0, %1;" : "=f"(c0[r]) : "f"(v0 * 0.5f));
            asm("tanh.approx.f32 %0, %1;" : "=f"(c1[r]) : "f"(v1 * 0.5f));
        }
        float v[16];
        #pragma unroll
        for (int px = 0; px < 32; px++) {
            float c2[3];
            #pragma unroll
            for (int r = 0; r < 3; r++) {
                uint32_t w = smw[SM_A + (r * 258 + pxb + px + 2) * APX + (c >> 1)];
                float vv = __half2float(__ushort_as_half((unsigned short)(w >> sh)));
                asm("tanh.approx.f32 %0, %1;" : "=f"(c2[r]) : "f"(vv * 0.5f));
            }
            float p = sd2;
            #pragma unroll
            for (int r = 0; r < 3; r++) {
                p = fmaf(dwr[r * 3 + 0], c0[r], p);
                p = fmaf(dwr[r * 3 + 1], c1[r], p);
                p = fmaf(dwr[r * 3 + 2], c2[r], p);
            }
            v[px & 15] = p;
            #pragma unroll
            for (int r = 0; r < 3; r++) { c0[r] = c1[r]; c1[r] = c2[r]; }

            if ((px & 15) == 15) {
                // fold upper half of lanes onto lower (same px set)
                #pragma unroll
                for (int i = 0; i < 16; i++)
                    v[i] += __shfl_xor_sync(0xFFFFFFFFu, v[i], 16);
                // 16x16 transpose-reduce
                #pragma unroll
                for (int i = 0; i < 8; i++) {
                    float snd = (lane & 8) ? v[i] : v[i+8];
                    float kpv = (lane & 8) ? v[i+8] : v[i];
                    v[i] = kpv + __shfl_xor_sync(0xFFFFFFFFu, snd, 8);
                }
                #pragma unroll
                for (int i = 0; i < 4; i++) {
                    float snd = (lane & 4) ? v[i] : v[i+4];
                    float kpv = (lane & 4) ? v[i+4] : v[i];
                    v[i] = kpv + __shfl_xor_sync(0xFFFFFFFFu, snd, 4);
                }
                #pragma unroll
                for (int i = 0; i < 2; i++) {
                    float snd = (lane & 2) ? v[i] : v[i+2];
                    float kpv = (lane & 2) ? v[i+2] : v[i];
                    v[i] = kpv + __shfl_xor_sync(0xFFFFFFFFu, snd, 2);
                }
                {
                    float snd = (lane & 1) ? v[0] : v[1];
                    float kpv = (lane & 1) ? v[1] : v[0];
                    v[0] = kpv + __shfl_xor_sync(0xFFFFFFFFu, snd, 1);
                }
                if (lane < 16) gs[pxb + (px & ~15) + lane] = v[0];
            }
        }
    }
    __syncthreads();

    // ================= mainloop: ldmatrix + mma (fp16) =================
    const uint32_t sbase = smem_u32(smraw);
    const uint32_t Abase = sbase + SM_A * 4;
    const uint32_t Bbase = sbase + SM_B * 4;
    const uint32_t laneA = ((((lane >> 3) & 1) * 8 + (lane & 7)) * APX + (lane >> 4) * 4) * 4;
    const uint32_t laneB = ((((lane >> 4) & 1) * 8 + (lane & 7)) * 12 + ((lane >> 3) & 1) * 4) * 4;

    float acc[2][4][4];
    #pragma unroll
    for (int mb = 0; mb < 2; mb++)
        #pragma unroll
        for (int nb = 0; nb < 4; nb++)
            #pragma unroll
            for (int r = 0; r < 4; r++) acc[mb][nb][r] = 0.0f;

    const int pxw = warp * 32;

    #pragma unroll 1
    for (int ki = 0; ki < 3; ki++) {
        #pragma unroll 1
        for (int kj = 0; kj < 3; kj++) {
            uint32_t aaddr = Abase + (uint32_t)((ki * 258 + pxw + kj) * APX * 4) + laneA;
            uint32_t baddr = Bbase + (uint32_t)((ki * 3 + kj) * 3072) + laneB;
            uint32_t a0[8], a1[8], b0q[8], b1q[8];
            ldsm4(a0[0], a0[1], a0[2], a0[3], aaddr);
            ldsm4(a0[4], a0[5], a0[6], a0[7], aaddr + 16 * APX * 4);
            ldsm4(b0q[0], b0q[1], b0q[2], b0q[3], baddr);
            ldsm4(b0q[4], b0q[5], b0q[6], b0q[7], baddr + 768);
            ldsm4(a1[0], a1[1], a1[2], a1[3], aaddr + 32);
            ldsm4(a1[4], a1[5], a1[6], a1[7], aaddr + 16 * APX * 4 + 32);
            ldsm4(b1q[0], b1q[1], b1q[2], b1q[3], baddr + 1536);
            ldsm4(b1q[4], b1q[5], b1q[6], b1q[7], baddr + 1536 + 768);
            #pragma unroll
            for (int mb = 0; mb < 2; mb++) {
                #pragma unroll
                for (int nb = 0; nb < 4; nb++)
                    mma16816(acc[mb][nb], a0[mb*4+0], a0[mb*4+1], a0[mb*4+2], a0[mb*4+3],
                             b0q[2*nb], b0q[2*nb+1]);
                #pragma unroll
                for (int nb = 0; nb < 4; nb++)
                    mma16816(acc[mb][nb], a1[mb*4+0], a1[mb*4+1], a1[mb*4+2], a1[mb*4+3],
                             b1q[2*nb], b1q[2*nb+1]);
            }
        }
    }

    // ================= epilogue: out = gate*acc + bias =================
    const int tig = lane & 3, grp = lane >> 2;
    float* ob = out + (size_t)b * O_ * HW_ * HW_ + (size_t)y * HW_;
    #pragma unroll
    for (int mb = 0; mb < 2; mb++) {
        int px = pxw + mb * 16 + grp;
        float g0 = gs[px], g1 = gs[px + 8];
        #pragma unroll
        for (int nb = 0; nb < 4; nb++) {
            int o = nb * 8 + tig * 2;
            float bi0 = bias_s[o], bi1 = bias_s[o + 1];
            ob[(size_t)o       * (HW_*HW_) + px]     = fmaf(g0, acc[mb][nb][0], bi0);
            ob[(size_t)(o + 1) * (HW_*HW_) + px]     = fmaf(g0, acc[mb][nb][1], bi1);
            ob[(size_t)o       * (HW_*HW_) + px + 8] = fmaf(g1, acc[mb][nb][2], bi0);
            ob[(size_t)(o + 1) * (HW_*HW_) + px + 8] = fmaf(g1, acc[mb][nb][3], bi1);
        }
    }
}

extern "C" void kernel_launch(void* const* d_in, const int* in_sizes, int n_in,
                              void* d_out, int out_size)
{
    const float* x       = (const float*)d_in[0];
    const float* weight  = (const float*)d_in[1];
    const float* dweight = (const float*)d_in[2];
    const float* bias    = (const float*)d_in[3];
    float* out = (float*)d_out;

    cudaFuncSetAttribute(dynamiconv_kernel,
                         cudaFuncAttributeMaxDynamicSharedMemorySize, SM_TOT_BYTES);

    dim3 grid(HW_, B_, 1);   // 256 rows x 8 batches = 2048 CTAs
    dynamiconv_kernel<<<grid, 256, SM_TOT_BYTES>>>(x, weight, dweight, bias, out);
}